// round 2
// baseline (speedup 1.0000x reference)
#include <cuda_runtime.h>
#include <math.h>

typedef unsigned long long ull;

#define BQ 8
#define AQ 3
#define HQ 200
#define WQ 304
#define HWQ (HQ*WQ)        // 60800
#define NQ (AQ*HWQ)        // 182400
#define NQ4 (NQ/4)         // 45600
#define KQ 2000
#define CAND_CAP 4096
#define BUCKET_CAP 6144
#define LOG_MAX_F 4.1351665567423560f
#define IMG_W 1216.0f
#define IMG_H 800.0f

#define OFF_SCORES 64000
#define OFF_KEEP   80000

// ---------------- device scratch (no allocs allowed) ----------------
__device__ int           g_selidx[BQ][KQ];
__device__ float         g_boxes[BQ][KQ][4];
__device__ unsigned char g_valid[BQ][KQ];

__device__ __forceinline__ unsigned fkey(float f) {
    unsigned u = __float_as_uint(f);
    return (u & 0x80000000u) ? ~u : (u | 0x80000000u);
}
__device__ __forceinline__ float unkey(unsigned u) {
    unsigned b = (u & 0x80000000u) ? (u & 0x7fffffffu) : ~u;
    return __uint_as_float(b);
}

// ================= Kernel A: exact top-2000 per batch =================
// grid = 8 (batch), block = 1024, dynamic smem = cand + bucket + hists
__global__ __launch_bounds__(1024, 1)
void k_topk(const float* __restrict__ cls, float* __restrict__ dout) {
    extern __shared__ unsigned char smem_raw[];
    ull* cand   = (ull*)smem_raw;                       // 4096
    ull* bucket = cand + CAND_CAP;                      // 6144
    unsigned (*hist)[256] = (unsigned(*)[256])(bucket + BUCKET_CAP); // 8 x 256

    __shared__ unsigned s_h[256];
    __shared__ int s_d1, s_need, s_d2;
    __shared__ int s_ncand, s_nbucket;

    const int b    = blockIdx.x;
    const int tid  = threadIdx.x;
    const int wid  = tid >> 5;
    const int lane = tid & 31;

    for (int i = tid; i < 8 * 256; i += 1024) ((unsigned*)hist)[i] = 0u;
    if (tid == 0) { s_ncand = 0; s_nbucket = 0; }
    __syncthreads();

    const float4* p4 = (const float4*)(cls + (size_t)b * NQ);

    // ---- pass 1: level-1 byte histogram ----
    for (int q4 = tid; q4 < NQ4; q4 += 1024) {
        float4 v = p4[q4];
        float vv[4] = {v.x, v.y, v.z, v.w};
        #pragma unroll
        for (int c = 0; c < 4; c++) {
            unsigned d = fkey(vv[c]) >> 24;
            unsigned mk = __match_any_sync(0xffffffffu, d);
            if ((__ffs(mk) - 1) == lane)
                atomicAdd(&hist[wid & 7][d], (unsigned)__popc(mk));
        }
    }
    __syncthreads();
    if (tid < 256) {
        unsigned s = 0;
        #pragma unroll
        for (int c = 0; c < 8; c++) s += hist[c][tid];
        s_h[tid] = s;
    }
    __syncthreads();
    if (tid == 0) {
        unsigned cum = 0; int d = 255;
        for (; d > 0; d--) {
            unsigned c = s_h[d];
            if (cum + c >= (unsigned)KQ) break;
            cum += c;
        }
        s_d1 = d; s_need = KQ - (int)cum;
    }
    __syncthreads();
    for (int i = tid; i < 8 * 256; i += 1024) ((unsigned*)hist)[i] = 0u;
    __syncthreads();

    const unsigned d1 = (unsigned)s_d1;

    // ---- pass 2: collect strictly-above into cand, bucket elems + level-2 hist ----
    for (int q4 = tid; q4 < NQ4; q4 += 1024) {
        float4 v = p4[q4];
        float vv[4] = {v.x, v.y, v.z, v.w};
        #pragma unroll
        for (int c = 0; c < 4; c++) {
            unsigned u = fkey(vv[c]);
            unsigned d = u >> 24;
            if (d < d1) continue;
            int q = q4 * 4 + c;
            int a = q / HWQ;
            int hw = q - a * HWQ;
            unsigned m = (unsigned)(hw * 3 + a);
            ull pk = ((ull)u << 32) | (unsigned)(~m);
            if (d > d1) {
                int p = atomicAdd(&s_ncand, 1);
                if (p < CAND_CAP) cand[p] = pk;
            } else {
                int p = atomicAdd(&s_nbucket, 1);
                if (p < BUCKET_CAP) bucket[p] = pk;
                atomicAdd(&hist[wid & 7][(u >> 16) & 255u], 1u);
            }
        }
    }
    __syncthreads();
    if (tid < 256) {
        unsigned s = 0;
        #pragma unroll
        for (int c = 0; c < 8; c++) s += hist[c][tid];
        s_h[tid] = s;
    }
    __syncthreads();
    if (tid == 0) {
        unsigned need = (unsigned)s_need;
        unsigned cum = 0; int d = 255;
        for (; d > 0; d--) {
            unsigned c = s_h[d];
            if (cum + c >= need) break;
            cum += c;
        }
        s_d2 = d;
    }
    __syncthreads();

    const unsigned d2 = (unsigned)s_d2;
    const int nb = min(s_nbucket, BUCKET_CAP);
    for (int t = tid; t < nb; t += 1024) {
        ull pk = bucket[t];
        if (((unsigned)(pk >> 48) & 255u) >= d2) {
            int p = atomicAdd(&s_ncand, 1);
            if (p < CAND_CAP) cand[p] = pk;
        }
    }
    __syncthreads();
    const int n = min(s_ncand, CAND_CAP);
    for (int t = n + tid; t < CAND_CAP; t += 1024) cand[t] = 0ull;
    __syncthreads();

    // ---- bitonic sort, descending (key desc, ~idx desc == idx asc on ties) ----
    for (int k2 = 2; k2 <= CAND_CAP; k2 <<= 1) {
        for (int j = k2 >> 1; j > 0; j >>= 1) {
            for (int i = tid; i < CAND_CAP; i += 1024) {
                int l = i ^ j;
                if (l > i) {
                    ull a = cand[i], bl = cand[l];
                    bool up = ((i & k2) == 0);
                    if (up ? (a < bl) : (a > bl)) { cand[i] = bl; cand[l] = a; }
                }
            }
            __syncthreads();
        }
    }

    for (int k = tid; k < KQ; k += 1024) {
        ull pk = cand[k];
        unsigned u = (unsigned)(pk >> 32);
        unsigned m = ~((unsigned)pk);
        g_selidx[b][k] = (int)m;
        dout[OFF_SCORES + b * KQ + k] = unkey(u);
    }
}

// ================= Kernel B: decode boxes =================
__global__ void k_decode(const float* __restrict__ regs) {
    int t = blockIdx.x * blockDim.x + threadIdx.x;
    if (t >= BQ * KQ) return;
    int b = t / KQ, k = t - b * KQ;
    int m = g_selidx[b][k];
    int a = m % 3, hw = m / 3;
    const float* base = regs + ((size_t)b * 12 + 4 * a) * HWQ + hw;
    float dx = base[0];
    float dy = base[HWQ];
    float dh = base[2 * HWQ];
    float dw = base[3 * HWQ];
    float s = (float)(32 << a);       // anchor width == height == size[a], exact
    float c = __fmul_rn(s, 0.5f);
    float px = __fadd_rn(c, __fmul_rn(dx, s));
    float py = __fadd_rn(c, __fmul_rn(dy, s));
    float ph = __fmul_rn(expf(fminf(dh, LOG_MAX_F)), s);
    float pw = __fmul_rn(expf(fminf(dw, LOG_MAX_F)), s);
    float hw2 = __fmul_rn(pw, 0.5f);
    float hh2 = __fmul_rn(ph, 0.5f);
    float x1 = __fsub_rn(px, hw2);
    float y1 = __fsub_rn(py, hh2);
    float x2 = __fadd_rn(px, hw2);
    float y2 = __fadd_rn(py, hh2);

    float bw = __fsub_rn(fminf(fmaxf(x2, 0.0f), IMG_W), fminf(fmaxf(x1, 0.0f), IMG_W));
    float bh = __fsub_rn(fminf(fmaxf(y2, 0.0f), IMG_H), fminf(fmaxf(y1, 0.0f), IMG_H));
    g_valid[b][k] = (bw >= 16.0f && bh >= 16.0f) ? 1 : 0;
    g_boxes[b][k][0] = x1;
    g_boxes[b][k][1] = y1;
    g_boxes[b][k][2] = x2;
    g_boxes[b][k][3] = y2;
}

// ================= Kernel C: greedy NMS + final write =================
__global__ __launch_bounds__(1024, 1)
void k_nms(float* __restrict__ dout) {
    __shared__ float sx1[KQ], sy1[KQ], sx2[KQ], sy2[KQ], sar[KQ];
    __shared__ unsigned keepw[64];
    __shared__ int s_i;

    const int b = blockIdx.x;
    const int tid = threadIdx.x;

    for (int k = tid; k < KQ; k += 1024) {
        float4 bx = *(const float4*)&g_boxes[b][k][0];
        sx1[k] = bx.x; sy1[k] = bx.y; sx2[k] = bx.z; sy2[k] = bx.w;
        sar[k] = __fmul_rn(__fsub_rn(bx.z, bx.x), __fsub_rn(bx.w, bx.y));
    }
    if (tid < 64) keepw[tid] = 0u;
    __syncthreads();
    for (int k = tid; k < KQ; k += 1024)
        if (g_valid[b][k]) atomicOr(&keepw[k >> 5], 1u << (k & 31));
    __syncthreads();
    if (tid == 0) {
        int nx = KQ;
        for (int w = 0; w < 63; w++) {
            unsigned word = keepw[w];
            if (word) { nx = w * 32 + __ffs(word) - 1; break; }
        }
        s_i = nx;
    }

    while (true) {
        __syncthreads();                 // publish s_i
        int i = s_i;
        if (i >= KQ) break;
        float ix1 = sx1[i], iy1 = sy1[i], ix2 = sx2[i], iy2 = sy2[i], ia = sar[i];
        for (int j = i + 1 + tid; j < KQ; j += 1024) {
            if ((keepw[j >> 5] >> (j & 31)) & 1u) {
                float iw = __fsub_rn(fminf(ix2, sx2[j]), fmaxf(ix1, sx1[j]));
                float ih = __fsub_rn(fminf(iy2, sy2[j]), fmaxf(iy1, sy1[j]));
                iw = fmaxf(iw, 0.0f);
                ih = fmaxf(ih, 0.0f);
                float inter = __fmul_rn(iw, ih);
                float un = __fsub_rn(__fadd_rn(ia, sar[j]), inter);
                float iou = __fdiv_rn(inter, fmaxf(un, 1e-6f));
                if (iou > 0.7f)
                    atomicAnd(&keepw[j >> 5], ~(1u << (j & 31)));
            }
        }
        __syncthreads();                 // suppression done
        if (tid == 0) {
            int nx = KQ;
            int w0 = (i + 1) >> 5;
            unsigned word = keepw[w0] & (0xffffffffu << ((i + 1) & 31));
            int w = w0;
            while (!word && ++w < 63) word = keepw[w];
            if (word && w < 63) nx = w * 32 + __ffs(word) - 1;
            s_i = nx;
        }
    }

    for (int k = tid; k < KQ; k += 1024) {
        float f = ((keepw[k >> 5] >> (k & 31)) & 1u) ? 1.0f : 0.0f;
        float* o = dout + (size_t)b * (KQ * 4) + k * 4;
        o[0] = sx1[k] * f;
        o[1] = sy1[k] * f;
        o[2] = sx2[k] * f;
        o[3] = sy2[k] * f;
        dout[OFF_KEEP + b * KQ + k] = f;
    }
}

// ================= launch =================
extern "C" void kernel_launch(void* const* d_in, const int* in_sizes, int n_in,
                              void* d_out, int out_size) {
    const float* cls  = (const float*)d_in[0];
    const float* regs = (const float*)d_in[1];
    float* dout = (float*)d_out;

    const int smemA = (CAND_CAP + BUCKET_CAP) * (int)sizeof(ull) + 8 * 256 * (int)sizeof(unsigned);
    cudaFuncSetAttribute(k_topk, cudaFuncAttributeMaxDynamicSharedMemorySize, smemA);

    k_topk<<<BQ, 1024, smemA>>>(cls, dout);
    k_decode<<<(BQ * KQ + 255) / 256, 256>>>(regs);
    k_nms<<<BQ, 1024>>>(dout);
}

// round 3
// speedup vs baseline: 1.1093x; 1.1093x over previous
#include <cuda_runtime.h>
#include <math.h>

typedef unsigned long long ull;

#define BQ 8
#define HWQ 60800
#define NQ 182400          // 3*200*304
#define NQ4 45600
#define SL 25              // slices per batch
#define CH4 1824           // float4 per slice (25*1824=45600)
#define KQ 2000
#define GCAND 4096
#define GBUCK 12288
#define SORTN 4096
#define LOG_MAX_F 4.1351665567423560f
#define IMG_W 1216.0f
#define IMG_H 800.0f
#define OFF_SCORES 64000
#define OFF_KEEP   80000
#define NWORDS 63          // ceil(2000/32)
#define WPW 8              // words per warp (8 warps * 8 = 64 >= 63)

// ---------------- device scratch ----------------
__device__ unsigned g_h1[BQ][256];
__device__ unsigned g_h2[BQ][256];
__device__ unsigned g_nc[BQ], g_nb[BQ];
__device__ int g_d1[BQ], g_need[BQ];
__device__ ull g_cand[BQ][GCAND];
__device__ ull g_buck[BQ][GBUCK];
__device__ float4 g_boxes[BQ][KQ];
__device__ unsigned char g_valid[BQ][KQ];

__device__ __forceinline__ unsigned fkey(float f) {
    unsigned u = __float_as_uint(f);
    return (u & 0x80000000u) ? ~u : (u | 0x80000000u);
}
__device__ __forceinline__ float unkey(unsigned u) {
    unsigned b = (u & 0x80000000u) ? (u & 0x7fffffffu) : ~u;
    return __uint_as_float(b);
}

// warp-aggregated append: returns slot or -1
__device__ __forceinline__ int wappend(unsigned* ctr, bool pred) {
    unsigned mask = __ballot_sync(0xffffffffu, pred);
    int pos = -1;
    if (pred) {
        int lane = threadIdx.x & 31;
        int leader = __ffs(mask) - 1;
        unsigned base = 0;
        if (lane == leader) base = atomicAdd(ctr, (unsigned)__popc(mask));
        base = __shfl_sync(mask, base, leader);
        pos = (int)(base + (unsigned)__popc(mask & ((1u << lane) - 1u)));
    }
    return pos;
}

// ================ K0: zero scratch ================
__global__ void k_zero() {
    int b = blockIdx.x, t = threadIdx.x;
    g_h1[b][t] = 0u;
    g_h2[b][t] = 0u;
    if (t == 0) { g_nc[b] = 0u; g_nb[b] = 0u; }
}

// ================ K1: level-1 histogram ================
__global__ __launch_bounds__(256) void k_hist1(const float* __restrict__ cls) {
    const int s = blockIdx.x, b = blockIdx.y;
    const int tid = threadIdx.x, wid = tid >> 5, lane = tid & 31;
    __shared__ unsigned h[8][256];
    for (int i = tid; i < 8 * 256; i += 256) ((unsigned*)h)[i] = 0u;
    __syncthreads();
    const float4* p4 = (const float4*)(cls + (size_t)b * NQ);
    for (int q4 = s * CH4 + tid; q4 < (s + 1) * CH4; q4 += 256) {
        float4 v = p4[q4];
        float vv[4] = {v.x, v.y, v.z, v.w};
        #pragma unroll
        for (int c = 0; c < 4; c++) {
            unsigned d = fkey(vv[c]) >> 24;
            unsigned mk = __match_any_sync(0xffffffffu, d);
            if ((__ffs(mk) - 1) == lane) atomicAdd(&h[wid][d], (unsigned)__popc(mk));
        }
    }
    __syncthreads();
    unsigned sum = 0;
    #pragma unroll
    for (int w = 0; w < 8; w++) sum += h[w][tid];
    if (sum) atomicAdd(&g_h1[b][tid], sum);
}

// ================ K2: thresholds (d1, need) ================
__global__ __launch_bounds__(256) void k_thr() {
    const int b = blockIdx.x, tid = threadIdx.x;
    __shared__ unsigned sh[256], ho[256];
    __shared__ int sd;
    unsigned v = g_h1[b][tid];
    ho[tid] = v; sh[tid] = v;
    if (tid == 0) sd = -1;
    __syncthreads();
    for (int ofs = 1; ofs < 256; ofs <<= 1) {
        unsigned u = (tid + ofs < 256) ? sh[tid + ofs] : 0u;
        __syncthreads();
        sh[tid] += u;
        __syncthreads();
    }
    if (sh[tid] >= (unsigned)KQ) atomicMax(&sd, tid);
    __syncthreads();
    if (tid == 0) {
        int d1 = sd;
        g_d1[b] = d1;
        g_need[b] = KQ - (int)(sh[d1] - ho[d1]);
    }
}

// ================ K3: compact + level-2 histogram ================
__global__ __launch_bounds__(256) void k_compact(const float* __restrict__ cls) {
    const int s = blockIdx.x, b = blockIdx.y;
    const int tid = threadIdx.x, wid = tid >> 5;
    __shared__ unsigned h[8][256];
    for (int i = tid; i < 8 * 256; i += 256) ((unsigned*)h)[i] = 0u;
    __syncthreads();
    const unsigned d1 = (unsigned)g_d1[b];
    const float4* p4 = (const float4*)(cls + (size_t)b * NQ);
    for (int q4 = s * CH4 + tid; q4 < (s + 1) * CH4; q4 += 256) {
        float4 v = p4[q4];
        float vv[4] = {v.x, v.y, v.z, v.w};
        #pragma unroll
        for (int c = 0; c < 4; c++) {
            unsigned u = fkey(vv[c]);
            unsigned d = u >> 24;
            bool p1 = (d > d1), p2 = (d == d1);
            ull pk = 0ull;
            if (p1 || p2) {
                int q = q4 * 4 + c;
                int a = q / HWQ;
                int hw = q - a * HWQ;
                unsigned m = (unsigned)(hw * 3 + a);
                pk = ((ull)u << 32) | (unsigned)(~m);
            }
            int pos = wappend(&g_nc[b], p1);
            if (p1 && pos < GCAND) g_cand[b][pos] = pk;
            int pos2 = wappend(&g_nb[b], p2);
            if (p2) {
                if (pos2 < GBUCK) g_buck[b][pos2] = pk;
                atomicAdd(&h[wid][(u >> 16) & 255u], 1u);
            }
        }
    }
    __syncthreads();
    unsigned sum = 0;
    #pragma unroll
    for (int w = 0; w < 8; w++) sum += h[w][tid];
    if (sum) atomicAdd(&g_h2[b][tid], sum);
}

// ================ K4: finalize select + sort + decode ================
__global__ __launch_bounds__(1024, 1)
void k_sortdec(const float* __restrict__ regs, float* __restrict__ dout) {
    __shared__ ull cand[SORTN];
    __shared__ unsigned sh[256], ho[256];
    __shared__ int sd2, s_n;
    const int b = blockIdx.x, tid = threadIdx.x;

    int ncand = (int)g_nc[b];
    if (ncand > GCAND) ncand = GCAND;
    for (int k = tid; k < ncand; k += 1024) cand[k] = g_cand[b][k];

    if (tid < 256) { unsigned v = g_h2[b][tid]; ho[tid] = v; sh[tid] = v; }
    if (tid == 0) { sd2 = -1; s_n = ncand; }
    __syncthreads();
    for (int ofs = 1; ofs < 256; ofs <<= 1) {
        unsigned u = (tid < 256 && tid + ofs < 256) ? sh[tid + ofs] : 0u;
        __syncthreads();
        if (tid < 256) sh[tid] += u;
        __syncthreads();
    }
    const int need = g_need[b];
    if (tid < 256 && sh[tid] >= (unsigned)need) atomicMax(&sd2, tid);
    __syncthreads();
    const unsigned d2 = (unsigned)sd2;

    int nb = (int)g_nb[b];
    if (nb > GBUCK) nb = GBUCK;
    for (int k = tid; k < nb; k += 1024) {
        ull pk = g_buck[b][k];
        if (((unsigned)(pk >> 48) & 255u) >= d2) {
            int p = atomicAdd(&s_n, 1);
            if (p < SORTN) cand[p] = pk;
        }
    }
    __syncthreads();
    const int ntot = min(s_n, SORTN);
    for (int k = tid; k < SORTN; k += 1024)
        if (k >= ntot) cand[k] = 0ull;
    __syncthreads();

    // bitonic sort descending
    for (int k2 = 2; k2 <= SORTN; k2 <<= 1) {
        for (int j = k2 >> 1; j > 0; j >>= 1) {
            for (int i = tid; i < SORTN; i += 1024) {
                int l = i ^ j;
                if (l > i) {
                    ull a = cand[i], bl = cand[l];
                    bool up = ((i & k2) == 0);
                    if (up ? (a < bl) : (a > bl)) { cand[i] = bl; cand[l] = a; }
                }
            }
            __syncthreads();
        }
    }

    // scores + decode
    for (int k = tid; k < KQ; k += 1024) {
        ull pk = cand[k];
        unsigned u = (unsigned)(pk >> 32);
        int m = (int)(~(unsigned)pk);
        dout[OFF_SCORES + b * KQ + k] = unkey(u);

        int a = m % 3, hw = m / 3;
        const float* base = regs + ((size_t)b * 12 + 4 * a) * HWQ + hw;
        float dx = base[0];
        float dy = base[HWQ];
        float dh = base[2 * HWQ];
        float dw = base[3 * HWQ];
        float s = (float)(32 << a);
        float c = __fmul_rn(s, 0.5f);
        float px = __fadd_rn(c, __fmul_rn(dx, s));
        float py = __fadd_rn(c, __fmul_rn(dy, s));
        float ph = __fmul_rn(expf(fminf(dh, LOG_MAX_F)), s);
        float pw = __fmul_rn(expf(fminf(dw, LOG_MAX_F)), s);
        float hw2 = __fmul_rn(pw, 0.5f);
        float hh2 = __fmul_rn(ph, 0.5f);
        float x1 = __fsub_rn(px, hw2);
        float y1 = __fsub_rn(py, hh2);
        float x2 = __fadd_rn(px, hw2);
        float y2 = __fadd_rn(py, hh2);
        float bw = __fsub_rn(fminf(fmaxf(x2, 0.0f), IMG_W), fminf(fmaxf(x1, 0.0f), IMG_W));
        float bh = __fsub_rn(fminf(fmaxf(y2, 0.0f), IMG_H), fminf(fmaxf(y1, 0.0f), IMG_H));
        g_valid[b][k] = (bw >= 16.0f && bh >= 16.0f) ? 1 : 0;
        g_boxes[b][k] = make_float4(x1, y1, x2, y2);
    }
}

// ================ K5: greedy NMS (register-resident, 1 bar/iter) ================
__global__ __launch_bounds__(256, 1)
void k_nms(float* __restrict__ dout) {
    __shared__ float4 sbox[KQ];
    __shared__ float sar[KQ];
    __shared__ int s_next[2];

    const int b = blockIdx.x, tid = threadIdx.x;
    const int wp = tid >> 5, lane = tid & 31;

    for (int k = tid; k < KQ; k += 256) {
        float4 v = g_boxes[b][k];
        sbox[k] = v;
        sar[k] = __fmul_rn(__fsub_rn(v.z, v.x), __fsub_rn(v.w, v.y));
    }
    if (tid < 2) s_next[tid] = KQ;

    unsigned word[WPW];
    float bx1[WPW], by1[WPW], bx2[WPW], by2[WPW], bar_[WPW];
    #pragma unroll
    for (int c = 0; c < WPW; c++) { bx1[c]=0.f; by1[c]=0.f; bx2[c]=0.f; by2[c]=0.f; bar_[c]=0.f; }
    __syncthreads();

    #pragma unroll
    for (int c = 0; c < WPW; c++) {
        int w = wp * WPW + c;
        int j = w * 32 + lane;
        bool v = (w < NWORDS && j < KQ) ? (g_valid[b][j] != 0) : false;
        word[c] = __ballot_sync(0xffffffffu, v);
        if (w < NWORDS && j < KQ) {
            float4 bb = sbox[j];
            bx1[c] = bb.x; by1[c] = bb.y; bx2[c] = bb.z; by2[c] = bb.w;
            bar_[c] = sar[j];
        }
    }

    int i = -1;
    int parity = 0;
    for (;;) {
        // scan own words for first alive index > i
        int cnd = KQ;
        #pragma unroll
        for (int c = 0; c < WPW; c++) {
            int base = (wp * WPW + c) * 32;
            if (base + 31 <= i) continue;
            unsigned m = word[c];
            if (base <= i) m &= (0xffffffffu << (i + 1 - base));
            if (m) { cnd = base + __ffs(m) - 1; break; }
        }
        if (lane == 0 && cnd < KQ) atomicMin(&s_next[parity], cnd);
        if (tid == 0) s_next[parity ^ 1] = KQ;
        __syncthreads();
        i = s_next[parity];
        parity ^= 1;
        if (i >= KQ) break;

        // suppress by box i
        float4 bi = sbox[i];
        float ia = sar[i];
        #pragma unroll
        for (int c = 0; c < WPW; c++) {
            int base = (wp * WPW + c) * 32;
            if (base + 31 <= i || word[c] == 0u) continue;   // warp-uniform
            int j = base + lane;
            bool act = ((word[c] >> lane) & 1u) && (j > i);
            float iw = fmaxf(__fsub_rn(fminf(bi.z, bx2[c]), fmaxf(bi.x, bx1[c])), 0.0f);
            float ih = fmaxf(__fsub_rn(fminf(bi.w, by2[c]), fmaxf(bi.y, by1[c])), 0.0f);
            float inter = __fmul_rn(iw, ih);
            float un = __fsub_rn(__fadd_rn(ia, bar_[c]), inter);
            float iou = __fdiv_rn(inter, fmaxf(un, 1e-6f));
            unsigned sup = __ballot_sync(0xffffffffu, act && (iou > 0.7f));
            word[c] &= ~sup;
        }
    }

    // final writes
    #pragma unroll
    for (int c = 0; c < WPW; c++) {
        int w = wp * WPW + c;
        int j = w * 32 + lane;
        if (w < NWORDS && j < KQ) {
            float f = ((word[c] >> lane) & 1u) ? 1.0f : 0.0f;
            float* o = dout + (size_t)b * (KQ * 4) + (size_t)j * 4;
            o[0] = bx1[c] * f;
            o[1] = by1[c] * f;
            o[2] = bx2[c] * f;
            o[3] = by2[c] * f;
            dout[OFF_KEEP + b * KQ + j] = f;
        }
    }
}

// ================ launch ================
extern "C" void kernel_launch(void* const* d_in, const int* in_sizes, int n_in,
                              void* d_out, int out_size) {
    const float* cls  = (const float*)d_in[0];
    const float* regs = (const float*)d_in[1];
    float* dout = (float*)d_out;

    k_zero<<<BQ, 256>>>();
    k_hist1<<<dim3(SL, BQ), 256>>>(cls);
    k_thr<<<BQ, 256>>>();
    k_compact<<<dim3(SL, BQ), 256>>>(cls);
    k_sortdec<<<BQ, 1024>>>(regs, dout);
    k_nms<<<BQ, 256>>>(dout);
}